// round 11
// baseline (speedup 1.0000x reference)
#include <cuda_runtime.h>
#include <cuda_fp16.h>
#include <cstdint>
#include <math.h>

// NeuralField fused: hashgrid encode + 3-layer MLP on mma.sync FP16 (fp32 acc)
// + final dot fused into the last epilogue.
// CTA = 128 points, 256 threads (8 warps), warp tile 64x64 (2 M x 4 N).
// Weights are pre-gathered (prep kernel) into per-thread fragment order in
// GLOBAL memory and loaded straight into registers with LDG.128 from L2 —
// no SMEM staging, no cp.async, no per-chunk barriers. Only 5 barriers/tile.

#define NLEV    8
#define NPTS    262144
#define THREADS 256

#define EPW  40        // E pitch in half2 words (80 halves); 40 % 32 == 8
#define BPW  136       // B1 pitch in half2 words (272 halves); 136 % 32 == 8

#define B1_OFF   0
#define E_OFF    (128 * BPW * 4)             // 69632
#define W3_OFF   (E_OFF + 128 * EPW * 4)     // 90112
#define PART_OFF (W3_OFF + 1024)             // 91136
#define SMEM_BYTES (PART_OFF + 2048)         // 93184

struct LevelParams { float scale[NLEV]; int res[NLEV]; int size[NLEV]; };

// fragment-major weights: 36 k16-groups x [nq(4)][j(4)][lane(32)][e(4)] half2
// groups 0..3 = layer0 (K=64), 4..19 = layer1, 20..35 = layer2
__device__ uint32_t g_Wf[36 * 2048];

// ------------------------------- helpers -----------------------------------
__device__ __forceinline__ void mma_f16(float* d, uint32_t a0, uint32_t a1,
                                        uint32_t a2, uint32_t a3,
                                        uint32_t b0, uint32_t b1) {
    asm volatile(
        "mma.sync.aligned.m16n8k16.row.col.f32.f16.f16.f32 "
        "{%0,%1,%2,%3}, {%4,%5,%6,%7}, {%8,%9}, {%0,%1,%2,%3};"
        : "+f"(d[0]), "+f"(d[1]), "+f"(d[2]), "+f"(d[3])
        : "r"(a0), "r"(a1), "r"(a2), "r"(a3), "r"(b0), "r"(b1));
}

__device__ __forceinline__ uint32_t packh2(float lo, float hi) {
    __half2 h = __halves2half2(__float2half_rn(lo), __float2half_rn(hi));
    return *(uint32_t*)&h;
}

// ---------------- prep: gather weights into fragment order (half2) ----------
__global__ void wt_prep(const float* __restrict__ W0,
                        const float* __restrict__ W1,
                        const float* __restrict__ W2)
{
    const int idx = blockIdx.x * 256 + threadIdx.x;    // 0 .. 73727
    if (idx >= 36 * 2048) return;
    const int g    = idx >> 11;          // k16-group 0..35
    const int r    = idx & 2047;
    const int nq   = r >> 9;
    const int j    = (r >> 7) & 3;
    const int lane = (r >> 2) & 31;
    const int e    = r & 3;
    const int grp  = lane >> 2, tig = lane & 3;
    const int i16  = j * 4 + e;
    const int nt   = i16 >> 1;
    const int b    = i16 & 1;

    const float* W; int kc;
    if (g < 4)       { W = W0; kc = g * 16; }
    else if (g < 20) { W = W1; kc = (g - 4) * 16; }
    else             { W = W2; kc = (g - 20) * 16; }

    const int k = kc + b * 8 + 2 * tig;                // halves (k, k+1)
    const int n = nq * 64 + nt * 8 + grp;
    g_Wf[idx] = packh2(W[k * 256 + n], W[(k + 1) * 256 + n]);
}

// --------------------------------- main kernel ------------------------------
__global__ __launch_bounds__(THREADS, 1)
void nf_main(const float* __restrict__ x, const float* __restrict__ table,
             const float* __restrict__ W3, float* __restrict__ out, LevelParams lp)
{
    extern __shared__ char smem[];
    uint32_t* B1w  = (uint32_t*)(smem + B1_OFF);   // half2 granularity
    uint32_t* Ew   = (uint32_t*)(smem + E_OFF);
    float*    W3s  = (float*)(smem + W3_OFF);
    float*    part = (float*)(smem + PART_OFF);

    const int tid  = threadIdx.x;
    const int wid  = tid >> 5;
    const int lane = tid & 31;
    const int grp  = lane >> 2;
    const int tig  = lane & 3;
    const int mb   = (wid & 1) * 64;
    const int nq   = wid >> 1;
    const int nb   = nq * 64;

    W3s[tid] = W3[tid];

    // ---------------- Encode: 2 threads/point, 4 levels/thread --------------
    // E k-permuted: level l, feature pair jp -> word (l>>1)*8 + 2*jp + (l&1)
    {
        const int p    = tid & 127;
        const int half = tid >> 7;
        const int gp   = blockIdx.x * 128 + p;
        const float xx = x[2 * gp];
        const float yy = x[2 * gp + 1];

        #pragma unroll
        for (int li = 0; li < 4; ++li) {
            const int l     = half * 4 + li;
            const float s   = lp.scale[l];
            const int res   = lp.res[l];
            const int size  = lp.size[l];

            const float posx = xx * s + 0.5f;
            const float posy = yy * s + 0.5f;
            const float gx = floorf(posx), gy = floorf(posy);
            const float fx = posx - gx,    fy = posy - gy;
            const int   ix = (int)gx,      iy = (int)gy;
            const float wx = fx * fx * (3.0f - 2.0f * fx);
            const float wy = fy * fy * (3.0f - 2.0f * fy);

            // batch: 4 corner addresses, then 8 gather loads, then accumulate
            float wc[4];
            const float4* tp[4];
            #pragma unroll
            for (int c = 0; c < 4; ++c) {
                const int dx = c >> 1, dy = c & 1;
                wc[c] = (dx ? wx : 1.0f - wx) * (dy ? wy : 1.0f - wy);
                int idx = (ix + dx) + (iy + dy) * res;   // < 2*size (dense)
                if (idx >= size) idx -= size;
                tp[c] = (const float4*)(table + ((size_t)(l * 8192 + idx) << 3));
            }
            float4 t0[4], t1[4];
            #pragma unroll
            for (int c = 0; c < 4; ++c) { t0[c] = __ldg(tp[c]); t1[c] = __ldg(tp[c] + 1); }

            float f[8];
            #pragma unroll
            for (int j = 0; j < 8; ++j) f[j] = 0.0f;
            #pragma unroll
            for (int c = 0; c < 4; ++c) {
                const float w = wc[c];
                f[0] += w * t0[c].x; f[1] += w * t0[c].y;
                f[2] += w * t0[c].z; f[3] += w * t0[c].w;
                f[4] += w * t1[c].x; f[5] += w * t1[c].y;
                f[6] += w * t1[c].z; f[7] += w * t1[c].w;
            }
            const int base = p * EPW + (l >> 1) * 8 + (l & 1);
            #pragma unroll
            for (int j = 0; j < 4; ++j)
                Ew[base + 2 * j] = packh2(f[2 * j], f[2 * j + 1]);
        }
    }
    __syncthreads();                      // E visible to all warps

    float acc[4][8][4];
    #pragma unroll
    for (int mt = 0; mt < 4; ++mt)
        #pragma unroll
        for (int nt = 0; nt < 8; ++nt)
            #pragma unroll
            for (int q = 0; q < 4; ++q) acc[mt][nt][q] = 0.0f;

    // B fragments straight from global (L2-resident), register double-buffer
    float bfB[2][16];

#define LOADB(GK, SLOT) do {                                                   \
    const float4* _s = ((const float4*)g_Wf) + ((GK) * 4 + nq) * 128 + lane;   \
    _Pragma("unroll")                                                          \
    for (int j = 0; j < 4; ++j)                                                \
        *(float4*)&bfB[SLOT][j * 4] = __ldg(_s + j * 32);                      \
} while (0)

#define RUN_LAYER(GBASE, NG, AW, APW) do {                                     \
    LOADB(GBASE, 0);                                                           \
    _Pragma("unroll 2")                                                        \
    for (int gi = 0; gi < (NG); ++gi) {                                        \
        const int cur = gi & 1;                                                \
        if (gi + 1 < (NG)) LOADB((GBASE) + gi + 1, cur ^ 1);                   \
        const int goff = gi * 8 + 2 * tig;                                     \
        uint32_t a[4][4];                                                      \
        _Pragma("unroll")                                                      \
        for (int mt = 0; mt < 4; ++mt) {                                       \
            const int r0 = (mb + mt * 16 + grp) * (APW) + goff;                \
            const uint2 u0 = *(const uint2*)&(AW)[r0];                         \
            const uint2 u1 = *(const uint2*)&(AW)[r0 + 8 * (APW)];             \
            a[mt][0] = u0.x; a[mt][1] = u1.x;                                  \
            a[mt][2] = u0.y; a[mt][3] = u1.y;                                  \
        }                                                                      \
        _Pragma("unroll")                                                      \
        for (int nt = 0; nt < 8; ++nt) {                                       \
            const uint32_t b0 = __float_as_uint(bfB[cur][nt * 2]);             \
            const uint32_t b1 = __float_as_uint(bfB[cur][nt * 2 + 1]);         \
            _Pragma("unroll")                                                  \
            for (int mt = 0; mt < 4; ++mt)                                     \
                mma_f16(acc[mt][nt], a[mt][0], a[mt][1], a[mt][2], a[mt][3],   \
                        b0, b1);                                               \
        }                                                                      \
    }                                                                          \
} while (0)

#define EPILOGUE_RELU() do {                                                   \
    _Pragma("unroll")                                                          \
    for (int mt = 0; mt < 4; ++mt)                                             \
        _Pragma("unroll")                                                      \
        for (int nt = 0; nt < 8; ++nt) {                                       \
            const int r0 = mb + mt * 16 + grp;                                 \
            const int c0 = nb + nt * 8 + 2 * tig;                              \
            const int t  = (c0 >> 1) & 7;                                      \
            const int q  = (t < 4) ? 2 * t : 2 * (t - 4) + 1;                  \
            const int w  = (c0 >> 4) * 8 + q;                                  \
            const uint32_t lo = packh2(fmaxf(acc[mt][nt][0], 0.0f),            \
                                       fmaxf(acc[mt][nt][1], 0.0f));           \
            const uint32_t hi = packh2(fmaxf(acc[mt][nt][2], 0.0f),            \
                                       fmaxf(acc[mt][nt][3], 0.0f));           \
            B1w[r0 * BPW + w]       = lo;                                      \
            B1w[(r0 + 8) * BPW + w] = hi;                                      \
            acc[mt][nt][0] = 0.0f; acc[mt][nt][1] = 0.0f;                      \
            acc[mt][nt][2] = 0.0f; acc[mt][nt][3] = 0.0f;                      \
        }                                                                      \
} while (0)

    // Layer 0: E[128x64] @ W0 -> B1 (ReLU). Writes don't alias E: no pre-bar.
    RUN_LAYER(0, 4, Ew, EPW);
    EPILOGUE_RELU();
    __syncthreads();

    // Layer 1: B1 @ W1 -> B1 in-place (barrier both sides of the overwrite).
    RUN_LAYER(4, 16, B1w, BPW);
    __syncthreads();
    EPILOGUE_RELU();
    __syncthreads();

    // Layer 2 + fused final dot from fp32 accumulators.
    RUN_LAYER(20, 16, B1w, BPW);
    #pragma unroll
    for (int mt = 0; mt < 4; ++mt) {
        float s0 = 0.0f, s1 = 0.0f;
        #pragma unroll
        for (int nt = 0; nt < 8; ++nt) {
            const int c = nb + nt * 8 + 2 * tig;
            const float wA = W3s[c], wB = W3s[c + 1];
            s0 = fmaf(fmaxf(acc[mt][nt][0], 0.0f), wA, s0);
            s0 = fmaf(fmaxf(acc[mt][nt][1], 0.0f), wB, s0);
            s1 = fmaf(fmaxf(acc[mt][nt][2], 0.0f), wA, s1);
            s1 = fmaf(fmaxf(acc[mt][nt][3], 0.0f), wB, s1);
        }
        s0 += __shfl_xor_sync(0xffffffffu, s0, 1);
        s0 += __shfl_xor_sync(0xffffffffu, s0, 2);
        s1 += __shfl_xor_sync(0xffffffffu, s1, 1);
        s1 += __shfl_xor_sync(0xffffffffu, s1, 2);
        if (tig == 0) {
            const int r0 = mb + mt * 16 + grp;
            part[r0 * 4 + nq]       = s0;
            part[(r0 + 8) * 4 + nq] = s1;
        }
    }
    __syncthreads();

    if (tid < 128) {
        const float* p4 = part + tid * 4;
        out[blockIdx.x * 128 + tid] = (p4[0] + p4[1]) + (p4[2] + p4[3]);
    }
}

// --------------------------------- launcher ---------------------------------
extern "C" void kernel_launch(void* const* d_in, const int* in_sizes, int n_in,
                              void* d_out, int out_size)
{
    const float* x     = (const float*)d_in[0];
    const float* table = (const float*)d_in[1];
    const float* W0    = (const float*)d_in[2];
    const float* W1    = (const float*)d_in[3];
    const float* W2    = (const float*)d_in[4];
    const float* W3    = (const float*)d_in[5];
    float*       out   = (float*)d_out;

    LevelParams lp;
    for (int l = 0; l < NLEV; ++l) {
        double sc = 16.0 * pow(1.2599210739135742, (double)l) - 1.0;
        int res = (int)ceil(sc) + 1;
        long long sz = (long long)res * (long long)res;
        sz = ((sz + 7) / 8) * 8;
        if (sz > (1LL << 19)) sz = 1LL << 19;
        lp.scale[l] = (float)sc;
        lp.res[l]   = res;
        lp.size[l]  = (int)sz;
    }

    wt_prep<<<288, 256>>>(W0, W1, W2);

    cudaFuncSetAttribute(nf_main, cudaFuncAttributeMaxDynamicSharedMemorySize,
                         SMEM_BYTES);
    nf_main<<<NPTS / 128, THREADS, SMEM_BYTES>>>(x, table, W3, out, lp);
}

// round 13
// speedup vs baseline: 1.1328x; 1.1328x over previous
#include <cuda_runtime.h>
#include <cuda_fp16.h>
#include <cstdint>
#include <math.h>

// NeuralField fused: hashgrid encode + 3-layer MLP on mma.sync FP16 (fp32 acc)
// + fused final dot. CTA = 64 points, 256 threads (8 warps), warp tile 32x64.
// 2 CTAs/SM (__launch_bounds__(256,2), 78KB smem, <=128 regs) so one CTA's
// serial phases overlap the other's mma stream. Weights streamed via cp.async
// double buffer, GROUP-MAJOR chunks: [kkI(2)][nq(4)][j(4)][lane(32)][e(4)].

#define NLEV    8
#define NPTS    262144
#define THREADS 256

#define EPW  40        // E pitch in half2 words (80 halves); 40 % 32 == 8
#define BPW  136       // B1 pitch in half2 words (272 halves); 136 % 32 == 8

#define B1_OFF   0                           // 64 x 136 words = 34816 B
#define E_OFF    (64 * BPW * 4)              // 34816
#define BS_OFF   (E_OFF + 64 * EPW * 4)      // 45056
#define BS_B     16384                       // bytes per weight chunk
#define W3_OFF   (BS_OFF + 2 * BS_B)         // 77824
#define PART_OFF (W3_OFF + 1024)             // 78848
#define SMEM_BYTES (PART_OFF + 1024)         // 79872  (2 CTAs fit in 228KB)

#define NCHUNK 18  // layer0: g 0..1 (K=64), layer1: 2..9, layer2: 10..17

struct LevelParams { float scale[NLEV]; int res[NLEV]; int size[NLEV]; };

// fragment-major weights (half2): 36 k16-groups x [nq(4)][j(4)][lane(32)][e(4)]
__device__ uint32_t g_Wf[36 * 2048];

// ------------------------------- helpers -----------------------------------
__device__ __forceinline__ uint32_t smem_u32(const void* p) {
    uint32_t a;
    asm("{ .reg .u64 t; cvta.to.shared.u64 t, %1; cvt.u32.u64 %0, t; }"
        : "=r"(a) : "l"(p));
    return a;
}
__device__ __forceinline__ void cp_async16(uint32_t dst, const void* src) {
    asm volatile("cp.async.cg.shared.global [%0], [%1], 16;" :: "r"(dst), "l"(src));
}
#define CP_COMMIT() asm volatile("cp.async.commit_group;" ::: "memory")
#define CP_WAIT0()  asm volatile("cp.async.wait_group 0;" ::: "memory")

__device__ __forceinline__ void mma_f16(float* d, uint32_t a0, uint32_t a1,
                                        uint32_t a2, uint32_t a3,
                                        uint32_t b0, uint32_t b1) {
    asm volatile(
        "mma.sync.aligned.m16n8k16.row.col.f32.f16.f16.f32 "
        "{%0,%1,%2,%3}, {%4,%5,%6,%7}, {%8,%9}, {%0,%1,%2,%3};"
        : "+f"(d[0]), "+f"(d[1]), "+f"(d[2]), "+f"(d[3])
        : "r"(a0), "r"(a1), "r"(a2), "r"(a3), "r"(b0), "r"(b1));
}

__device__ __forceinline__ uint32_t packh2(float lo, float hi) {
    __half2 h = __halves2half2(__float2half_rn(lo), __float2half_rn(hi));
    return *(uint32_t*)&h;
}

// ---------------- prep: gather weights into fragment order (half2) ----------
// layout: [group g (36)][nq(4)][j(4)][lane(32)][e(4)]
__global__ void wt_prep(const float* __restrict__ W0,
                        const float* __restrict__ W1,
                        const float* __restrict__ W2)
{
    const int idx = blockIdx.x * 256 + threadIdx.x;    // 0 .. 73727
    if (idx >= 36 * 2048) return;
    const int g    = idx >> 11;          // k16-group 0..35
    const int r    = idx & 2047;
    const int nq   = r >> 9;
    const int j    = (r >> 7) & 3;
    const int lane = (r >> 2) & 31;
    const int e    = r & 3;
    const int grp  = lane >> 2, tig = lane & 3;
    const int i16  = j * 4 + e;
    const int nt   = i16 >> 1;
    const int b    = i16 & 1;

    const float* W; int kc;
    if (g < 4)       { W = W0; kc = g * 16; }
    else if (g < 20) { W = W1; kc = (g - 4) * 16; }
    else             { W = W2; kc = (g - 20) * 16; }

    const int k = kc + b * 8 + 2 * tig;                // halves (k, k+1)
    const int n = nq * 64 + nt * 8 + grp;
    g_Wf[idx] = packh2(W[k * 256 + n], W[(k + 1) * 256 + n]);
}

// --------------------------------- main kernel ------------------------------
__device__ __forceinline__ void prefetch_chunk(int g, uint32_t bs_base, int tid)
{
    const uint32_t* src = g_Wf + g * 4096;             // chunk g = groups 2g,2g+1
    const uint32_t dst = bs_base + (uint32_t)(g & 1) * BS_B;
    #pragma unroll
    for (int it = 0; it < 4; ++it) {
        const int i = tid + it * 256;                  // 0..1023 float4s
        cp_async16(dst + (uint32_t)i * 16, src + i * 4);
    }
    CP_COMMIT();
}

__global__ __launch_bounds__(THREADS, 2)
void nf_main(const float* __restrict__ x, const float* __restrict__ table,
             const float* __restrict__ W3, float* __restrict__ out, LevelParams lp)
{
    extern __shared__ char smem[];
    uint32_t* B1w  = (uint32_t*)(smem + B1_OFF);   // half2 granularity
    uint32_t* Ew   = (uint32_t*)(smem + E_OFF);
    float*    W3s  = (float*)(smem + W3_OFF);
    float*    part = (float*)(smem + PART_OFF);
    const uint32_t bs_base = smem_u32(smem + BS_OFF);

    const int tid  = threadIdx.x;
    const int wid  = tid >> 5;
    const int lane = tid & 31;
    const int grp  = lane >> 2;
    const int tig  = lane & 3;
    const int mb   = (wid & 1) * 32;     // M-half base row (of 64)
    const int nq   = wid >> 1;           // N-quarter
    const int nb   = nq * 64;

    prefetch_chunk(0, bs_base, tid);     // overlaps encode

    W3s[tid] = W3[tid];

    // ---------------- Encode: 4 threads/point, 2 levels/thread --------------
    // E k-permuted in half2: level l, pair jp -> word (l>>1)*8 + 2*jp + (l&1)
    {
        const int p    = tid & 63;
        const int quad = tid >> 6;           // 0..3 -> levels {2q, 2q+1}
        const int gp   = blockIdx.x * 64 + p;
        const float xx = x[2 * gp];
        const float yy = x[2 * gp + 1];

        #pragma unroll
        for (int li = 0; li < 2; ++li) {
            const int l     = quad * 2 + li;
            const float s   = lp.scale[l];
            const int res   = lp.res[l];
            const int size  = lp.size[l];

            const float posx = xx * s + 0.5f;
            const float posy = yy * s + 0.5f;
            const float gx = floorf(posx), gy = floorf(posy);
            const float fx = posx - gx,    fy = posy - gy;
            const int   ix = (int)gx,      iy = (int)gy;
            const float wx = fx * fx * (3.0f - 2.0f * fx);
            const float wy = fy * fy * (3.0f - 2.0f * fy);

            float f[8];
            #pragma unroll
            for (int j = 0; j < 8; ++j) f[j] = 0.0f;

            #pragma unroll
            for (int dx = 0; dx < 2; ++dx) {
                const float wxx = dx ? wx : (1.0f - wx);
                #pragma unroll
                for (int dy = 0; dy < 2; ++dy) {
                    const float wyy = dy ? wy : (1.0f - wy);
                    int idx = (ix + dx) + (iy + dy) * res;   // < 2*size (dense)
                    if (idx >= size) idx -= size;
                    const float4* tp =
                        (const float4*)(table + ((size_t)(l * 8192 + idx) << 3));
                    const float w = wxx * wyy;
                    const float4 t0 = tp[0];
                    const float4 t1 = tp[1];
                    f[0] += w * t0.x; f[1] += w * t0.y;
                    f[2] += w * t0.z; f[3] += w * t0.w;
                    f[4] += w * t1.x; f[5] += w * t1.y;
                    f[6] += w * t1.z; f[7] += w * t1.w;
                }
            }
            const int base = p * EPW + (l >> 1) * 8 + (l & 1);
            #pragma unroll
            for (int j = 0; j < 4; ++j)
                Ew[base + 2 * j] = packh2(f[2 * j], f[2 * j + 1]);
        }
    }

    // ---------------- 18 chunks across 3 layers ------------------------------
    float acc[2][8][4];
    #pragma unroll
    for (int mt = 0; mt < 2; ++mt)
        #pragma unroll
        for (int nt = 0; nt < 8; ++nt)
            #pragma unroll
            for (int q = 0; q < 4; ++q) acc[mt][nt][q] = 0.0f;

    for (int g = 0; g < NCHUNK; ++g) {
        CP_WAIT0();
        __syncthreads();
        if (g + 1 < NCHUNK) prefetch_chunk(g + 1, bs_base, tid);

        const int layer = (g < 2) ? 0 : ((g < 10) ? 1 : 2);
        const int gch   = (layer == 0) ? g : ((layer == 1) ? g - 2 : g - 10);
        const uint32_t* Aw = (layer == 0) ? Ew : B1w;
        const int apw      = (layer == 0) ? EPW : BPW;
        const uint32_t* Bs = (const uint32_t*)(smem + BS_OFF + (g & 1) * BS_B);

        #pragma unroll
        for (int kkI = 0; kkI < 2; ++kkI) {
            const int goff = (gch * 2 + kkI) * 8 + 2 * tig;  // k16-group base word
            uint32_t a[2][4];
            #pragma unroll
            for (int mt = 0; mt < 2; ++mt) {
                const int r0 = (mb + mt * 16 + grp) * apw + goff;
                const uint2 u0 = *(const uint2*)&Aw[r0];            // a0, a2
                const uint2 u1 = *(const uint2*)&Aw[r0 + 8 * apw];  // a1, a3
                a[mt][0] = u0.x; a[mt][1] = u1.x;
                a[mt][2] = u0.y; a[mt][3] = u1.y;
            }
            // GROUP-MAJOR chunk: kkI stride 2048 words, nq stride 512 words
            float bf[16];
            #pragma unroll
            for (int j = 0; j < 4; ++j)
                *(float4*)&bf[j * 4] = *(const float4*)
                    &Bs[kkI * 2048 + nq * 512 + j * 128 + lane * 4];

            #pragma unroll
            for (int nt = 0; nt < 8; ++nt) {
                const uint32_t b0 = __float_as_uint(bf[nt * 2]);
                const uint32_t b1 = __float_as_uint(bf[nt * 2 + 1]);
                #pragma unroll
                for (int mt = 0; mt < 2; ++mt)
                    mma_f16(acc[mt][nt], a[mt][0], a[mt][1], a[mt][2], a[mt][3],
                            b0, b1);
            }
        }

        if (g == 1 || g == 9) {
            if (g == 9) __syncthreads();   // layer1 read B1 -> in-place write
            // ReLU + half2 pack, k-permuted for next layer's A reads
            #pragma unroll
            for (int mt = 0; mt < 2; ++mt)
                #pragma unroll
                for (int nt = 0; nt < 8; ++nt) {
                    const int r0 = mb + mt * 16 + grp;
                    const int c0 = nb + nt * 8 + 2 * tig;
                    const int t  = (c0 >> 1) & 7;
                    const int q  = (t < 4) ? 2 * t : 2 * (t - 4) + 1;
                    const int w  = (c0 >> 4) * 8 + q;
                    const uint32_t lo = packh2(fmaxf(acc[mt][nt][0], 0.0f),
                                               fmaxf(acc[mt][nt][1], 0.0f));
                    const uint32_t hi = packh2(fmaxf(acc[mt][nt][2], 0.0f),
                                               fmaxf(acc[mt][nt][3], 0.0f));
                    B1w[r0 * BPW + w]       = lo;
                    B1w[(r0 + 8) * BPW + w] = hi;
                    acc[mt][nt][0] = 0.0f; acc[mt][nt][1] = 0.0f;
                    acc[mt][nt][2] = 0.0f; acc[mt][nt][3] = 0.0f;
                }
        } else if (g == 17) {
            // Fused final: out[r] = sum_c relu(h3[r,c]) * W3[c], from fp32 acc
            #pragma unroll
            for (int mt = 0; mt < 2; ++mt) {
                float s0 = 0.0f, s1 = 0.0f;
                #pragma unroll
                for (int nt = 0; nt < 8; ++nt) {
                    const int c = nb + nt * 8 + 2 * tig;
                    const float wA = W3s[c], wB = W3s[c + 1];
                    s0 = fmaf(fmaxf(acc[mt][nt][0], 0.0f), wA, s0);
                    s0 = fmaf(fmaxf(acc[mt][nt][1], 0.0f), wB, s0);
                    s1 = fmaf(fmaxf(acc[mt][nt][2], 0.0f), wA, s1);
                    s1 = fmaf(fmaxf(acc[mt][nt][3], 0.0f), wB, s1);
                }
                s0 += __shfl_xor_sync(0xffffffffu, s0, 1);
                s0 += __shfl_xor_sync(0xffffffffu, s0, 2);
                s1 += __shfl_xor_sync(0xffffffffu, s1, 1);
                s1 += __shfl_xor_sync(0xffffffffu, s1, 2);
                if (tig == 0) {
                    const int r0 = mb + mt * 16 + grp;
                    part[r0 * 4 + nq]       = s0;
                    part[(r0 + 8) * 4 + nq] = s1;
                }
            }
        }
    }
    __syncthreads();

    if (tid < 64) {
        const float* p4 = part + tid * 4;
        out[blockIdx.x * 64 + tid] = (p4[0] + p4[1]) + (p4[2] + p4[3]);
    }
}

// --------------------------------- launcher ---------------------------------
extern "C" void kernel_launch(void* const* d_in, const int* in_sizes, int n_in,
                              void* d_out, int out_size)
{
    const float* x     = (const float*)d_in[0];
    const float* table = (const float*)d_in[1];
    const float* W0    = (const float*)d_in[2];
    const float* W1    = (const float*)d_in[3];
    const float* W2    = (const float*)d_in[4];
    const float* W3    = (const float*)d_in[5];
    float*       out   = (float*)d_out;

    LevelParams lp;
    for (int l = 0; l < NLEV; ++l) {
        double sc = 16.0 * pow(1.2599210739135742, (double)l) - 1.0;
        int res = (int)ceil(sc) + 1;
        long long sz = (long long)res * (long long)res;
        sz = ((sz + 7) / 8) * 8;
        if (sz > (1LL << 19)) sz = 1LL << 19;
        lp.scale[l] = (float)sc;
        lp.res[l]   = res;
        lp.size[l]  = (int)sz;
    }

    wt_prep<<<288, 256>>>(W0, W1, W2);

    cudaFuncSetAttribute(nf_main, cudaFuncAttributeMaxDynamicSharedMemorySize,
                         SMEM_BYTES);
    nf_main<<<NPTS / 64, THREADS, SMEM_BYTES>>>(x, table, W3, out, lp);
}

// round 14
// speedup vs baseline: 1.2361x; 1.0913x over previous
#include <cuda_runtime.h>
#include <cuda_fp16.h>
#include <cstdint>
#include <math.h>

// NeuralField fused: hashgrid encode + 3-layer MLP on mma.sync FP16 (fp32 acc)
// + fused final dot. CTA = 64 points, 256 threads (8 warps), warp tile 32x64.
// 2 CTAs/SM (__launch_bounds__(256,2), 48KB smem, <=128 regs).
// Weights pre-gathered to per-thread fragment order in GLOBAL memory and
// LDG.128'd straight to registers (L2-resident) with a cross-layer
// register double-buffer. No cp.async, no weight SMEM, 5 barriers/tile.

#define NLEV    8
#define NPTS    262144
#define THREADS 256

#define EPW  40        // E pitch in half2 words (80 halves); 40 % 32 == 8
#define BPW  136       // B1 pitch in half2 words (272 halves); 136 % 32 == 8

#define B1_OFF   0                           // 64 x 136 words = 34816 B
#define E_OFF    (64 * BPW * 4)              // 34816
#define W3_OFF   (E_OFF + 64 * EPW * 4)      // 45056
#define PART_OFF (W3_OFF + 1024)             // 46080
#define SMEM_BYTES (PART_OFF + 1024)         // 47104  (2 CTAs/SM trivially)

struct LevelParams { float scale[NLEV]; int res[NLEV]; int size[NLEV]; };

// fragment-major weights (half2): [g(36)][nq(4)][j(4)][lane(32)][e(4)]
// groups 0..3 = layer0 (K=64), 4..19 = layer1, 20..35 = layer2
__device__ uint32_t g_Wf[36 * 2048];

// ------------------------------- helpers -----------------------------------
__device__ __forceinline__ void mma_f16(float* d, uint32_t a0, uint32_t a1,
                                        uint32_t a2, uint32_t a3,
                                        uint32_t b0, uint32_t b1) {
    asm volatile(
        "mma.sync.aligned.m16n8k16.row.col.f32.f16.f16.f32 "
        "{%0,%1,%2,%3}, {%4,%5,%6,%7}, {%8,%9}, {%0,%1,%2,%3};"
        : "+f"(d[0]), "+f"(d[1]), "+f"(d[2]), "+f"(d[3])
        : "r"(a0), "r"(a1), "r"(a2), "r"(a3), "r"(b0), "r"(b1));
}

__device__ __forceinline__ uint32_t packh2(float lo, float hi) {
    __half2 h = __halves2half2(__float2half_rn(lo), __float2half_rn(hi));
    return *(uint32_t*)&h;
}

// ---------------- prep: gather weights into fragment order (half2) ----------
__global__ void wt_prep(const float* __restrict__ W0,
                        const float* __restrict__ W1,
                        const float* __restrict__ W2)
{
    const int idx = blockIdx.x * 256 + threadIdx.x;    // 0 .. 73727
    if (idx >= 36 * 2048) return;
    const int g    = idx >> 11;          // k16-group 0..35
    const int r    = idx & 2047;
    const int nq   = r >> 9;
    const int j    = (r >> 7) & 3;
    const int lane = (r >> 2) & 31;
    const int e    = r & 3;
    const int grp  = lane >> 2, tig = lane & 3;
    const int i16  = j * 4 + e;
    const int nt   = i16 >> 1;
    const int b    = i16 & 1;

    const float* W; int kc;
    if (g < 4)       { W = W0; kc = g * 16; }
    else if (g < 20) { W = W1; kc = (g - 4) * 16; }
    else             { W = W2; kc = (g - 20) * 16; }

    const int k = kc + b * 8 + 2 * tig;                // halves (k, k+1)
    const int n = nq * 64 + nt * 8 + grp;
    g_Wf[idx] = packh2(W[k * 256 + n], W[(k + 1) * 256 + n]);
}

// --------------------------------- main kernel ------------------------------
__global__ __launch_bounds__(THREADS, 2)
void nf_main(const float* __restrict__ x, const float* __restrict__ table,
             const float* __restrict__ W3, float* __restrict__ out, LevelParams lp)
{
    extern __shared__ char smem[];
    uint32_t* B1w  = (uint32_t*)(smem + B1_OFF);   // half2 granularity
    uint32_t* Ew   = (uint32_t*)(smem + E_OFF);
    float*    W3s  = (float*)(smem + W3_OFF);
    float*    part = (float*)(smem + PART_OFF);

    const int tid  = threadIdx.x;
    const int wid  = tid >> 5;
    const int lane = tid & 31;
    const int grp  = lane >> 2;
    const int tig  = lane & 3;
    const int mb   = (wid & 1) * 32;     // M-half base row (of 64)
    const int nq   = wid >> 1;           // N-quarter
    const int nb   = nq * 64;

    W3s[tid] = W3[tid];

    // ---------------- Encode: 4 threads/point, 2 levels/thread --------------
    // E k-permuted in half2: level l, pair jp -> word (l>>1)*8 + 2*jp + (l&1)
    {
        const int p    = tid & 63;
        const int quad = tid >> 6;           // 0..3 -> levels {2q, 2q+1}
        const int gp   = blockIdx.x * 64 + p;
        const float xx = x[2 * gp];
        const float yy = x[2 * gp + 1];

        #pragma unroll
        for (int li = 0; li < 2; ++li) {
            const int l     = quad * 2 + li;
            const float s   = lp.scale[l];
            const int res   = lp.res[l];
            const int size  = lp.size[l];

            const float posx = xx * s + 0.5f;
            const float posy = yy * s + 0.5f;
            const float gx = floorf(posx), gy = floorf(posy);
            const float fx = posx - gx,    fy = posy - gy;
            const int   ix = (int)gx,      iy = (int)gy;
            const float wx = fx * fx * (3.0f - 2.0f * fx);
            const float wy = fy * fy * (3.0f - 2.0f * fy);

            float f[8];
            #pragma unroll
            for (int j = 0; j < 8; ++j) f[j] = 0.0f;

            #pragma unroll
            for (int dx = 0; dx < 2; ++dx) {
                const float wxx = dx ? wx : (1.0f - wx);
                #pragma unroll
                for (int dy = 0; dy < 2; ++dy) {
                    const float wyy = dy ? wy : (1.0f - wy);
                    int idx = (ix + dx) + (iy + dy) * res;   // < 2*size (dense)
                    if (idx >= size) idx -= size;
                    const float4* tp =
                        (const float4*)(table + ((size_t)(l * 8192 + idx) << 3));
                    const float w = wxx * wyy;
                    const float4 t0 = tp[0];
                    const float4 t1 = tp[1];
                    f[0] += w * t0.x; f[1] += w * t0.y;
                    f[2] += w * t0.z; f[3] += w * t0.w;
                    f[4] += w * t1.x; f[5] += w * t1.y;
                    f[6] += w * t1.z; f[7] += w * t1.w;
                }
            }
            const int base = p * EPW + (l >> 1) * 8 + (l & 1);
            #pragma unroll
            for (int j = 0; j < 4; ++j)
                Ew[base + 2 * j] = packh2(f[2 * j], f[2 * j + 1]);
        }
    }

    float acc[2][8][4];
    #pragma unroll
    for (int mt = 0; mt < 2; ++mt)
        #pragma unroll
        for (int nt = 0; nt < 8; ++nt)
            #pragma unroll
            for (int q = 0; q < 4; ++q) acc[mt][nt][q] = 0.0f;

    // B fragments straight from global (L2-resident), register double-buffer.
    float bf[2][16];

#define LOADB(G, SLOT) do {                                                    \
    const float4* _s = ((const float4*)g_Wf) + (G) * 512 + nq * 128 + lane;    \
    *(float4*)&bf[SLOT][0]  = __ldg(_s);                                       \
    *(float4*)&bf[SLOT][4]  = __ldg(_s + 32);                                  \
    *(float4*)&bf[SLOT][8]  = __ldg(_s + 64);                                  \
    *(float4*)&bf[SLOT][12] = __ldg(_s + 96);                                  \
} while (0)

    // prefetch group 0 before the encode barrier (no dependence on E)
    LOADB(0, 0);
    __syncthreads();                      // E visible to all warps

#define RUN_LAYER(GBASE, NG, AW, APW) do {                                     \
    _Pragma("unroll 2")                                                        \
    for (int lg = 0; lg < (NG); ++lg) {                                        \
        const int cur = ((GBASE) + lg) & 1;                                    \
        if ((GBASE) + lg + 1 < 36) LOADB((GBASE) + lg + 1, cur ^ 1);           \
        const int goff = lg * 8 + 2 * tig;                                     \
        uint32_t a[2][4];                                                      \
        _Pragma("unroll")                                                      \
        for (int mt = 0; mt < 2; ++mt) {                                       \
            const int r0 = (mb + mt * 16 + grp) * (APW) + goff;                \
            const uint2 u0 = *(const uint2*)&(AW)[r0];                         \
            const uint2 u1 = *(const uint2*)&(AW)[r0 + 8 * (APW)];             \
            a[mt][0] = u0.x; a[mt][1] = u1.x;                                  \
            a[mt][2] = u0.y; a[mt][3] = u1.y;                                  \
        }                                                                      \
        _Pragma("unroll")                                                      \
        for (int nt = 0; nt < 8; ++nt) {                                       \
            const uint32_t b0 = __float_as_uint(bf[cur][nt * 2]);              \
            const uint32_t b1 = __float_as_uint(bf[cur][nt * 2 + 1]);          \
            _Pragma("unroll")                                                  \
            for (int mt = 0; mt < 2; ++mt)                                     \
                mma_f16(acc[mt][nt], a[mt][0], a[mt][1], a[mt][2], a[mt][3],   \
                        b0, b1);                                               \
        }                                                                      \
    }                                                                          \
} while (0)

#define EPILOGUE_RELU() do {                                                   \
    _Pragma("unroll")                                                          \
    for (int mt = 0; mt < 2; ++mt)                                             \
        _Pragma("unroll")                                                      \
        for (int nt = 0; nt < 8; ++nt) {                                       \
            const int r0 = mb + mt * 16 + grp;                                 \
            const int c0 = nb + nt * 8 + 2 * tig;                              \
            const int t  = (c0 >> 1) & 7;                                      \
            const int q  = (t < 4) ? 2 * t : 2 * (t - 4) + 1;                  \
            const int w  = (c0 >> 4) * 8 + q;                                  \
            const uint32_t lo = packh2(fmaxf(acc[mt][nt][0], 0.0f),            \
                                       fmaxf(acc[mt][nt][1], 0.0f));           \
            const uint32_t hi = packh2(fmaxf(acc[mt][nt][2], 0.0f),            \
                                       fmaxf(acc[mt][nt][3], 0.0f));           \
            B1w[r0 * BPW + w]       = lo;                                      \
            B1w[(r0 + 8) * BPW + w] = hi;                                      \
            acc[mt][nt][0] = 0.0f; acc[mt][nt][1] = 0.0f;                      \
            acc[mt][nt][2] = 0.0f; acc[mt][nt][3] = 0.0f;                      \
        }                                                                      \
} while (0)

    // Layer 0: E[64x64] @ W0 -> B1 (ReLU). B1 doesn't alias E.
    RUN_LAYER(0, 4, Ew, EPW);
    EPILOGUE_RELU();
    __syncthreads();

    // Layer 1: B1 @ W1 -> B1 in-place (barrier both sides of overwrite).
    RUN_LAYER(4, 16, B1w, BPW);
    __syncthreads();
    EPILOGUE_RELU();
    __syncthreads();

    // Layer 2 + fused final dot from fp32 accumulators.
    RUN_LAYER(20, 16, B1w, BPW);
    #pragma unroll
    for (int mt = 0; mt < 2; ++mt) {
        float s0 = 0.0f, s1 = 0.0f;
        #pragma unroll
        for (int nt = 0; nt < 8; ++nt) {
            const int c = nb + nt * 8 + 2 * tig;
            const float wA = W3s[c], wB = W3s[c + 1];
            s0 = fmaf(fmaxf(acc[mt][nt][0], 0.0f), wA, s0);
            s0 = fmaf(fmaxf(acc[mt][nt][1], 0.0f), wB, s0);
            s1 = fmaf(fmaxf(acc[mt][nt][2], 0.0f), wA, s1);
            s1 = fmaf(fmaxf(acc[mt][nt][3], 0.0f), wB, s1);
        }
        s0 += __shfl_xor_sync(0xffffffffu, s0, 1);
        s0 += __shfl_xor_sync(0xffffffffu, s0, 2);
        s1 += __shfl_xor_sync(0xffffffffu, s1, 1);
        s1 += __shfl_xor_sync(0xffffffffu, s1, 2);
        if (tig == 0) {
            const int r0 = mb + mt * 16 + grp;
            part[r0 * 4 + nq]       = s0;
            part[(r0 + 8) * 4 + nq] = s1;
        }
    }
    __syncthreads();

    if (tid < 64) {
        const float* p4 = part + tid * 4;
        out[blockIdx.x * 64 + tid] = (p4[0] + p4[1]) + (p4[2] + p4[3]);
    }
}

// --------------------------------- launcher ---------------------------------
extern "C" void kernel_launch(void* const* d_in, const int* in_sizes, int n_in,
                              void* d_out, int out_size)
{
    const float* x     = (const float*)d_in[0];
    const float* table = (const float*)d_in[1];
    const float* W0    = (const float*)d_in[2];
    const float* W1    = (const float*)d_in[3];
    const float* W2    = (const float*)d_in[4];
    const float* W3    = (const float*)d_in[5];
    float*       out   = (float*)d_out;

    LevelParams lp;
    for (int l = 0; l < NLEV; ++l) {
        double sc = 16.0 * pow(1.2599210739135742, (double)l) - 1.0;
        int res = (int)ceil(sc) + 1;
        long long sz = (long long)res * (long long)res;
        sz = ((sz + 7) / 8) * 8;
        if (sz > (1LL << 19)) sz = 1LL << 19;
        lp.scale[l] = (float)sc;
        lp.res[l]   = res;
        lp.size[l]  = (int)sz;
    }

    wt_prep<<<288, 256>>>(W0, W1, W2);

    cudaFuncSetAttribute(nf_main, cudaFuncAttributeMaxDynamicSharedMemorySize,
                         SMEM_BYTES);
    nf_main<<<NPTS / 64, THREADS, SMEM_BYTES>>>(x, table, W3, out, lp);
}

// round 15
// speedup vs baseline: 1.3191x; 1.0671x over previous
#include <cuda_runtime.h>
#include <cuda_fp16.h>
#include <cstdint>
#include <math.h>

// NeuralField fused: hashgrid encode + 3-layer MLP on mma.sync FP16 (fp32 acc)
// + fused final dot. CTA = 64 points, 256 threads (8 warps), warp tile 32x64.
// 2 CTAs/SM (__launch_bounds__(256,2), 48KB smem, <=128 regs).
// Weights pre-gathered to fragment order in GLOBAL memory, LDG.128'd straight
// to registers. THIS ROUND: table pre-converted to fp16 -> each encode corner
// is ONE scattered LDG.128 instead of two (halves encode L1 wavefronts).

#define NLEV    8
#define NPTS    262144
#define THREADS 256

#define EPW  40        // E pitch in half2 words (80 halves); 40 % 32 == 8
#define BPW  136       // B1 pitch in half2 words (272 halves); 136 % 32 == 8

#define B1_OFF   0                           // 64 x 136 words = 34816 B
#define E_OFF    (64 * BPW * 4)              // 34816
#define W3_OFF   (E_OFF + 64 * EPW * 4)      // 45056
#define PART_OFF (W3_OFF + 1024)             // 46080
#define SMEM_BYTES (PART_OFF + 1024)         // 47104  (2 CTAs/SM trivially)

struct LevelParams { float scale[NLEV]; int res[NLEV]; int size[NLEV]; };

// fragment-major weights (half2): [g(36)][nq(4)][j(4)][lane(32)][e(4)]
__device__ uint32_t g_Wf[36 * 2048];
// fp16 table: one uint4 (8 halves) per (level, row)
__device__ uint4 g_Th[NLEV * 8192];

// ------------------------------- helpers -----------------------------------
__device__ __forceinline__ void mma_f16(float* d, uint32_t a0, uint32_t a1,
                                        uint32_t a2, uint32_t a3,
                                        uint32_t b0, uint32_t b1) {
    asm volatile(
        "mma.sync.aligned.m16n8k16.row.col.f32.f16.f16.f32 "
        "{%0,%1,%2,%3}, {%4,%5,%6,%7}, {%8,%9}, {%0,%1,%2,%3};"
        : "+f"(d[0]), "+f"(d[1]), "+f"(d[2]), "+f"(d[3])
        : "r"(a0), "r"(a1), "r"(a2), "r"(a3), "r"(b0), "r"(b1));
}

__device__ __forceinline__ uint32_t packh2(float lo, float hi) {
    __half2 h = __halves2half2(__float2half_rn(lo), __float2half_rn(hi));
    return *(uint32_t*)&h;
}

// ---------------- prep: weights to fragment order + table to fp16 -----------
__global__ void wt_prep(const float* __restrict__ W0,
                        const float* __restrict__ W1,
                        const float* __restrict__ W2)
{
    const int idx = blockIdx.x * 256 + threadIdx.x;    // 0 .. 73727
    if (idx >= 36 * 2048) return;
    const int g    = idx >> 11;          // k16-group 0..35
    const int r    = idx & 2047;
    const int nq   = r >> 9;
    const int j    = (r >> 7) & 3;
    const int lane = (r >> 2) & 31;
    const int e    = r & 3;
    const int grp  = lane >> 2, tig = lane & 3;
    const int i16  = j * 4 + e;
    const int nt   = i16 >> 1;
    const int b    = i16 & 1;

    const float* W; int kc;
    if (g < 4)       { W = W0; kc = g * 16; }
    else if (g < 20) { W = W1; kc = (g - 4) * 16; }
    else             { W = W2; kc = (g - 20) * 16; }

    const int k = kc + b * 8 + 2 * tig;                // halves (k, k+1)
    const int n = nq * 64 + nt * 8 + grp;
    g_Wf[idx] = packh2(W[k * 256 + n], W[(k + 1) * 256 + n]);
}

__global__ void tb_prep(const float* __restrict__ table)
{
    const int r = blockIdx.x * 256 + threadIdx.x;      // 0 .. 65535 rows
    const float4 t0 = ((const float4*)table)[r * 2];
    const float4 t1 = ((const float4*)table)[r * 2 + 1];
    uint4 v;
    v.x = packh2(t0.x, t0.y);
    v.y = packh2(t0.z, t0.w);
    v.z = packh2(t1.x, t1.y);
    v.w = packh2(t1.z, t1.w);
    g_Th[r] = v;
}

// --------------------------------- main kernel ------------------------------
__global__ __launch_bounds__(THREADS, 2)
void nf_main(const float* __restrict__ x,
             const float* __restrict__ W3, float* __restrict__ out, LevelParams lp)
{
    extern __shared__ char smem[];
    uint32_t* B1w  = (uint32_t*)(smem + B1_OFF);   // half2 granularity
    uint32_t* Ew   = (uint32_t*)(smem + E_OFF);
    float*    W3s  = (float*)(smem + W3_OFF);
    float*    part = (float*)(smem + PART_OFF);

    const int tid  = threadIdx.x;
    const int wid  = tid >> 5;
    const int lane = tid & 31;
    const int grp  = lane >> 2;
    const int tig  = lane & 3;
    const int mb   = (wid & 1) * 32;     // M-half base row (of 64)
    const int nq   = wid >> 1;           // N-quarter
    const int nb   = nq * 64;

    W3s[tid] = W3[tid];

    // ---------------- Encode: 4 threads/point, 2 levels/thread --------------
    // E k-permuted in half2: level l, pair jp -> word (l>>1)*8 + 2*jp + (l&1)
    {
        const int p    = tid & 63;
        const int quad = tid >> 6;           // 0..3 -> levels {2q, 2q+1}
        const int gp   = blockIdx.x * 64 + p;
        const float xx = x[2 * gp];
        const float yy = x[2 * gp + 1];

        #pragma unroll
        for (int li = 0; li < 2; ++li) {
            const int l     = quad * 2 + li;
            const float s   = lp.scale[l];
            const int res   = lp.res[l];
            const int size  = lp.size[l];

            const float posx = xx * s + 0.5f;
            const float posy = yy * s + 0.5f;
            const float gx = floorf(posx), gy = floorf(posy);
            const float fx = posx - gx,    fy = posy - gy;
            const int   ix = (int)gx,      iy = (int)gy;
            const float wx = fx * fx * (3.0f - 2.0f * fx);
            const float wy = fy * fy * (3.0f - 2.0f * fy);

            // 4 corners: one LDG.128 each (fp16 table row = 16B)
            float wc[4];
            uint4 v[4];
            #pragma unroll
            for (int c = 0; c < 4; ++c) {
                const int dx = c >> 1, dy = c & 1;
                wc[c] = (dx ? wx : 1.0f - wx) * (dy ? wy : 1.0f - wy);
                int idx = (ix + dx) + (iy + dy) * res;   // < 2*size (dense)
                if (idx >= size) idx -= size;
                v[c] = __ldg(&g_Th[l * 8192 + idx]);
            }

            float f[8];
            #pragma unroll
            for (int j = 0; j < 8; ++j) f[j] = 0.0f;
            #pragma unroll
            for (int c = 0; c < 4; ++c) {
                const float w = wc[c];
                const __half2* h = (const __half2*)&v[c];
                const float2 p0 = __half22float2(h[0]);
                const float2 p1 = __half22float2(h[1]);
                const float2 p2 = __half22float2(h[2]);
                const float2 p3 = __half22float2(h[3]);
                f[0] += w * p0.x; f[1] += w * p0.y;
                f[2] += w * p1.x; f[3] += w * p1.y;
                f[4] += w * p2.x; f[5] += w * p2.y;
                f[6] += w * p3.x; f[7] += w * p3.y;
            }
            const int base = p * EPW + (l >> 1) * 8 + (l & 1);
            #pragma unroll
            for (int j = 0; j < 4; ++j)
                Ew[base + 2 * j] = packh2(f[2 * j], f[2 * j + 1]);
        }
    }

    float acc[2][8][4];
    #pragma unroll
    for (int mt = 0; mt < 2; ++mt)
        #pragma unroll
        for (int nt = 0; nt < 8; ++nt)
            #pragma unroll
            for (int q = 0; q < 4; ++q) acc[mt][nt][q] = 0.0f;

    // B fragments straight from global (L2-resident), register double-buffer.
    float bf[2][16];

#define LOADB(G, SLOT) do {                                                    \
    const float4* _s = ((const float4*)g_Wf) + (G) * 512 + nq * 128 + lane;    \
    *(float4*)&bf[SLOT][0]  = __ldg(_s);                                       \
    *(float4*)&bf[SLOT][4]  = __ldg(_s + 32);                                  \
    *(float4*)&bf[SLOT][8]  = __ldg(_s + 64);                                  \
    *(float4*)&bf[SLOT][12] = __ldg(_s + 96);                                  \
} while (0)

    // prefetch group 0 before the encode barrier (no dependence on E)
    LOADB(0, 0);
    __syncthreads();                      // E visible to all warps

#define RUN_LAYER(GBASE, NG, AW, APW) do {                                     \
    _Pragma("unroll 2")                                                        \
    for (int lg = 0; lg < (NG); ++lg) {                                        \
        const int cur = ((GBASE) + lg) & 1;                                    \
        if ((GBASE) + lg + 1 < 36) LOADB((GBASE) + lg + 1, cur ^ 1);           \
        const int goff = lg * 8 + 2 * tig;                                     \
        uint32_t a[2][4];                                                      \
        _Pragma("unroll")                                                      \
        for (int mt = 0; mt < 2; ++mt) {                                       \
            const int r0 = (mb + mt * 16 + grp) * (APW) + goff;                \
            const uint2 u0 = *(const uint2*)&(AW)[r0];                         \
            const uint2 u1 = *(const uint2*)&(AW)[r0 + 8 * (APW)];             \
            a[mt][0] = u0.x; a[mt][1] = u1.x;                                  \
            a[mt][2] = u0.y; a[mt][3] = u1.y;                                  \
        }                                                                      \
        _Pragma("unroll")                                                      \
        for (int nt = 0; nt < 8; ++nt) {                                       \
            const uint32_t b0 = __float_as_uint(bf[cur][nt * 2]);              \
            const uint32_t b1 = __float_as_uint(bf[cur][nt * 2 + 1]);          \
            _Pragma("unroll")                                                  \
            for (int mt = 0; mt < 2; ++mt)                                     \
                mma_f16(acc[mt][nt], a[mt][0], a[mt][1], a[mt][2], a[mt][3],   \
                        b0, b1);                                               \
        }                                                                      \
    }                                                                          \
} while (0)

#define EPILOGUE_RELU() do {                                                   \
    _Pragma("unroll")                                                          \
    for (int mt = 0; mt < 2; ++mt)                                             \
        _Pragma("unroll")                                                      \
        for (int nt = 0; nt < 8; ++nt) {                                       \
            const int r0 = mb + mt * 16 + grp;                                 \
            const int c0 = nb + nt * 8 + 2 * tig;                              \
            const int t  = (c0 >> 1) & 7;                                      \
            const int q  = (t < 4) ? 2 * t : 2 * (t - 4) + 1;                  \
            const int w  = (c0 >> 4) * 8 + q;                                  \
            const uint32_t lo = packh2(fmaxf(acc[mt][nt][0], 0.0f),            \
                                       fmaxf(acc[mt][nt][1], 0.0f));           \
            const uint32_t hi = packh2(fmaxf(acc[mt][nt][2], 0.0f),            \
                                       fmaxf(acc[mt][nt][3], 0.0f));           \
            B1w[r0 * BPW + w]       = lo;                                      \
            B1w[(r0 + 8) * BPW + w] = hi;                                      \
            acc[mt][nt][0] = 0.0f; acc[mt][nt][1] = 0.0f;                      \
            acc[mt][nt][2] = 0.0f; acc[mt][nt][3] = 0.0f;                      \
        }                                                                      \
} while (0)

    // Layer 0: E[64x64] @ W0 -> B1 (ReLU). B1 doesn't alias E.
    RUN_LAYER(0, 4, Ew, EPW);
    EPILOGUE_RELU();
    __syncthreads();

    // Layer 1: B1 @ W1 -> B1 in-place (barrier both sides of overwrite).
    RUN_LAYER(4, 16, B1w, BPW);
    __syncthreads();
    EPILOGUE_RELU();
    __syncthreads();

    // Layer 2 + fused final dot from fp32 accumulators.
    RUN_LAYER(20, 16, B1w, BPW);
    #pragma unroll
    for (int mt = 0; mt < 2; ++mt) {
        float s0 = 0.0f, s1 = 0.0f;
        #pragma unroll
        for (int nt = 0; nt < 8; ++nt) {
            const int c = nb + nt * 8 + 2 * tig;
            const float wA = W3s[c], wB = W3s[c + 1];
            s0 = fmaf(fmaxf(acc[mt][nt][0], 0.0f), wA, s0);
            s0 = fmaf(fmaxf(acc[mt][nt][1], 0.0f), wB, s0);
            s1 = fmaf(fmaxf(acc[mt][nt][2], 0.0f), wA, s1);
            s1 = fmaf(fmaxf(acc[mt][nt][3], 0.0f), wB, s1);
        }
        s0 += __shfl_xor_sync(0xffffffffu, s0, 1);
        s0 += __shfl_xor_sync(0xffffffffu, s0, 2);
        s1 += __shfl_xor_sync(0xffffffffu, s1, 1);
        s1 += __shfl_xor_sync(0xffffffffu, s1, 2);
        if (tig == 0) {
            const int r0 = mb + mt * 16 + grp;
            part[r0 * 4 + nq]       = s0;
            part[(r0 + 8) * 4 + nq] = s1;
        }
    }
    __syncthreads();

    if (tid < 64) {
        const float* p4 = part + tid * 4;
        out[blockIdx.x * 64 + tid] = (p4[0] + p4[1]) + (p4[2] + p4[3]);
    }
}

// --------------------------------- launcher ---------------------------------
extern "C" void kernel_launch(void* const* d_in, const int* in_sizes, int n_in,
                              void* d_out, int out_size)
{
    const float* x     = (const float*)d_in[0];
    const float* table = (const float*)d_in[1];
    const float* W0    = (const float*)d_in[2];
    const float* W1    = (const float*)d_in[3];
    const float* W2    = (const float*)d_in[4];
    const float* W3    = (const float*)d_in[5];
    float*       out   = (float*)d_out;

    LevelParams lp;
    for (int l = 0; l < NLEV; ++l) {
        double sc = 16.0 * pow(1.2599210739135742, (double)l) - 1.0;
        int res = (int)ceil(sc) + 1;
        long long sz = (long long)res * (long long)res;
        sz = ((sz + 7) / 8) * 8;
        if (sz > (1LL << 19)) sz = 1LL << 19;
        lp.scale[l] = (float)sc;
        lp.res[l]   = res;
        lp.size[l]  = (int)sz;
    }

    wt_prep<<<288, 256>>>(W0, W1, W2);
    tb_prep<<<256, 256>>>(table);

    cudaFuncSetAttribute(nf_main, cudaFuncAttributeMaxDynamicSharedMemorySize,
                         SMEM_BYTES);
    nf_main<<<NPTS / 64, THREADS, SMEM_BYTES>>>(x, W3, out, lp);
}

// round 16
// speedup vs baseline: 1.6414x; 1.2443x over previous
#include <cuda_runtime.h>
#include <cuda_fp16.h>
#include <cstdint>
#include <math.h>

// NeuralField fused: hashgrid encode + 3-layer MLP on mma.sync FP16 (fp32 acc)
// + fused final dot. CTA = 64 points, 256 threads (8 warps), warp tile 32x64.
// 2 CTAs/SM. Weights LDG.128'd from fragment-major global (L2-resident).
// THIS ROUND: natural-order XOR-swizzled activation buffers (pitch 128/32
// words, w ^= (row&7)<<2 on 16B blocks), A fragments via ldmatrix.x4,
// encode stores via STS.128, ping-pong B1->B2 (4 barriers total).

#define NLEV    8
#define NPTS    262144
#define THREADS 256

#define BPITCH 128     // B1/B2 words per row (256 halves)
#define EPITCH 32      // E words per row (64 halves)

#define B1_OFF   0
#define B2_OFF   32768
#define E_OFF    65536
#define W3_OFF   73728
#define PART_OFF 74752
#define SMEM_BYTES 75776     // 2 CTAs/SM (<=113KB each)

struct LevelParams { float scale[NLEV]; int res[NLEV]; int size[NLEV]; };

// fragment-major weights (half2): [g(36)][nq(4)][j(4)][lane(32)][e(4)]
__device__ uint32_t g_Wf[36 * 2048];
// fp16 table: one uint4 (8 halves) per (level, row)
__device__ uint4 g_Th[NLEV * 8192];

// ------------------------------- helpers -----------------------------------
__device__ __forceinline__ uint32_t smem_u32(const void* p) {
    uint32_t a;
    asm("{ .reg .u64 t; cvta.to.shared.u64 t, %1; cvt.u32.u64 %0, t; }"
        : "=r"(a) : "l"(p));
    return a;
}
__device__ __forceinline__ void mma_f16(float* d, uint32_t a0, uint32_t a1,
                                        uint32_t a2, uint32_t a3,
                                        uint32_t b0, uint32_t b1) {
    asm volatile(
        "mma.sync.aligned.m16n8k16.row.col.f32.f16.f16.f32 "
        "{%0,%1,%2,%3}, {%4,%5,%6,%7}, {%8,%9}, {%0,%1,%2,%3};"
        : "+f"(d[0]), "+f"(d[1]), "+f"(d[2]), "+f"(d[3])
        : "r"(a0), "r"(a1), "r"(a2), "r"(a3), "r"(b0), "r"(b1));
}
__device__ __forceinline__ void ldsm4(uint32_t* r, uint32_t addr) {
    asm volatile("ldmatrix.sync.aligned.m8n8.x4.shared.b16 {%0,%1,%2,%3}, [%4];"
                 : "=r"(r[0]), "=r"(r[1]), "=r"(r[2]), "=r"(r[3]) : "r"(addr));
}
__device__ __forceinline__ uint32_t packh2(float lo, float hi) {
    __half2 h = __halves2half2(__float2half_rn(lo), __float2half_rn(hi));
    return *(uint32_t*)&h;
}

// ---------------- prep: weights to fragment order + table to fp16 -----------
__global__ void wt_prep(const float* __restrict__ W0,
                        const float* __restrict__ W1,
                        const float* __restrict__ W2)
{
    const int idx = blockIdx.x * 256 + threadIdx.x;    // 0 .. 73727
    if (idx >= 36 * 2048) return;
    const int g    = idx >> 11;          // k16-group 0..35
    const int r    = idx & 2047;
    const int nq   = r >> 9;
    const int j    = (r >> 7) & 3;
    const int lane = (r >> 2) & 31;
    const int e    = r & 3;
    const int grp  = lane >> 2, tig = lane & 3;
    const int i16  = j * 4 + e;
    const int nt   = i16 >> 1;
    const int b    = i16 & 1;

    const float* W; int kc;
    if (g < 4)       { W = W0; kc = g * 16; }
    else if (g < 20) { W = W1; kc = (g - 4) * 16; }
    else             { W = W2; kc = (g - 20) * 16; }

    const int k = kc + b * 8 + 2 * tig;                // halves (k, k+1)
    const int n = nq * 64 + nt * 8 + grp;
    g_Wf[idx] = packh2(W[k * 256 + n], W[(k + 1) * 256 + n]);
}

__global__ void tb_prep(const float* __restrict__ table)
{
    const int r = blockIdx.x * 256 + threadIdx.x;      // 0 .. 65535 rows
    const float4 t0 = ((const float4*)table)[r * 2];
    const float4 t1 = ((const float4*)table)[r * 2 + 1];
    uint4 v;
    v.x = packh2(t0.x, t0.y);
    v.y = packh2(t0.z, t0.w);
    v.z = packh2(t1.x, t1.y);
    v.w = packh2(t1.z, t1.w);
    g_Th[r] = v;
}

// --------------------------------- main kernel ------------------------------
__global__ __launch_bounds__(THREADS, 2)
void nf_main(const float* __restrict__ x,
             const float* __restrict__ W3, float* __restrict__ out, LevelParams lp)
{
    extern __shared__ char smem[];
    uint32_t* B1w  = (uint32_t*)(smem + B1_OFF);
    uint32_t* B2w  = (uint32_t*)(smem + B2_OFF);
    uint32_t* Ew   = (uint32_t*)(smem + E_OFF);
    float*    W3s  = (float*)(smem + W3_OFF);
    float*    part = (float*)(smem + PART_OFF);
    const uint32_t sb = smem_u32(smem);

    const int tid  = threadIdx.x;
    const int wid  = tid >> 5;
    const int lane = tid & 31;
    const int grp  = lane >> 2;
    const int tig  = lane & 3;
    const int mb   = (wid & 1) * 32;     // M-half base row (of 64)
    const int nq   = wid >> 1;           // N-quarter
    const int nb   = nq * 64;

    // ldmatrix per-lane constants
    const int lrow = lane & 15;          // row within m16 tile
    const int l4   = (lane >> 4) << 2;   // 16B-block select (0 or 4 words)
    const int swz  = (lane & 7) << 2;    // XOR swizzle term ((row&7)<<2)

    W3s[tid] = W3[tid];

    // ---------------- Encode: 4 threads/point, 2 levels/thread --------------
    // Natural order: level l -> words l*4..l*4+3; phys = p*32 + (w ^ ((p&7)<<2))
    {
        const int p    = tid & 63;
        const int quad = tid >> 6;           // 0..3 -> levels {2q, 2q+1}
        const int gp   = blockIdx.x * 64 + p;
        const float xx = x[2 * gp];
        const float yy = x[2 * gp + 1];
        const int psw  = (p & 7) << 2;

        #pragma unroll
        for (int li = 0; li < 2; ++li) {
            const int l     = quad * 2 + li;
            const float s   = lp.scale[l];
            const int res   = lp.res[l];
            const int size  = lp.size[l];

            const float posx = xx * s + 0.5f;
            const float posy = yy * s + 0.5f;
            const float gx = floorf(posx), gy = floorf(posy);
            const float fx = posx - gx,    fy = posy - gy;
            const int   ix = (int)gx,      iy = (int)gy;
            const float wx = fx * fx * (3.0f - 2.0f * fx);
            const float wy = fy * fy * (3.0f - 2.0f * fy);

            float wc[4];
            uint4 v[4];
            #pragma unroll
            for (int c = 0; c < 4; ++c) {
                const int dx = c >> 1, dy = c & 1;
                wc[c] = (dx ? wx : 1.0f - wx) * (dy ? wy : 1.0f - wy);
                int idx = (ix + dx) + (iy + dy) * res;   // < 2*size (dense)
                if (idx >= size) idx -= size;
                v[c] = __ldg(&g_Th[l * 8192 + idx]);
            }

            float f[8];
            #pragma unroll
            for (int j = 0; j < 8; ++j) f[j] = 0.0f;
            #pragma unroll
            for (int c = 0; c < 4; ++c) {
                const float w = wc[c];
                const __half2* h = (const __half2*)&v[c];
                const float2 p0 = __half22float2(h[0]);
                const float2 p1 = __half22float2(h[1]);
                const float2 p2 = __half22float2(h[2]);
                const float2 p3 = __half22float2(h[3]);
                f[0] += w * p0.x; f[1] += w * p0.y;
                f[2] += w * p1.x; f[3] += w * p1.y;
                f[4] += w * p2.x; f[5] += w * p2.y;
                f[6] += w * p3.x; f[7] += w * p3.y;
            }
            uint4 uv;
            uv.x = packh2(f[0], f[1]);
            uv.y = packh2(f[2], f[3]);
            uv.z = packh2(f[4], f[5]);
            uv.w = packh2(f[6], f[7]);
            const int physw = p * EPITCH + ((l * 4) ^ psw);
            *(uint4*)&Ew[physw] = uv;                    // STS.128, conflict-free
        }
    }

    float acc[2][8][4];
    #pragma unroll
    for (int mt = 0; mt < 2; ++mt)
        #pragma unroll
        for (int nt = 0; nt < 8; ++nt)
            #pragma unroll
            for (int q = 0; q < 4; ++q) acc[mt][nt][q] = 0.0f;

    // B fragments straight from global (L2-resident), register double-buffer.
    float bf[2][16];

#define LOADB(G, SLOT) do {                                                    \
    const float4* _s = ((const float4*)g_Wf) + (G) * 512 + nq * 128 + lane;    \
    *(float4*)&bf[SLOT][0]  = __ldg(_s);                                       \
    *(float4*)&bf[SLOT][4]  = __ldg(_s + 32);                                  \
    *(float4*)&bf[SLOT][8]  = __ldg(_s + 64);                                  \
    *(float4*)&bf[SLOT][12] = __ldg(_s + 96);                                  \
} while (0)

    LOADB(0, 0);
    __syncthreads();                      // (1) E visible to all warps

#define RUN_LAYER(GBASE, NG, ABYTE, APITCH) do {                               \
    const uint32_t rb0 = (ABYTE) + (uint32_t)(mb + lrow) * ((APITCH) * 4);     \
    const uint32_t rb1 = rb0 + 16u * ((APITCH) * 4);                           \
    _Pragma("unroll 2")                                                        \
    for (int lg = 0; lg < (NG); ++lg) {                                        \
        const int cur = ((GBASE) + lg) & 1;                                    \
        if ((GBASE) + lg + 1 < 36) LOADB((GBASE) + lg + 1, cur ^ 1);           \
        const uint32_t wsw = (uint32_t)((lg * 8 + l4) ^ swz) << 2;             \
        uint32_t a[2][4];                                                      \
        ldsm4(a[0], rb0 + wsw);                                                \
        ldsm4(a[1], rb1 + wsw);                                                \
        _Pragma("unroll")                                                      \
        for (int nt = 0; nt < 8; ++nt) {                                       \
            const uint32_t b0 = __float_as_uint(bf[cur][nt * 2]);              \
            const uint32_t b1 = __float_as_uint(bf[cur][nt * 2 + 1]);          \
            _Pragma("unroll")                                                  \
            for (int mt = 0; mt < 2; ++mt)                                     \
                mma_f16(acc[mt][nt], a[mt][0], a[mt][1], a[mt][2], a[mt][3],   \
                        b0, b1);                                               \
        }                                                                      \
    }                                                                          \
} while (0)

#define EPILOGUE_RELU(DW) do {                                                 \
    _Pragma("unroll")                                                          \
    for (int mt = 0; mt < 2; ++mt)                                             \
        _Pragma("unroll")                                                      \
        for (int nt = 0; nt < 8; ++nt) {                                       \
            const int r0 = mb + mt * 16 + grp;                                 \
            const int w  = nq * 32 + nt * 4 + tig;                             \
            const int ph = r0 * BPITCH + (w ^ (grp << 2));                     \
            (DW)[ph]              = packh2(fmaxf(acc[mt][nt][0], 0.0f),        \
                                           fmaxf(acc[mt][nt][1], 0.0f));       \
            (DW)[ph + 8 * BPITCH] = packh2(fmaxf(acc[mt][nt][2], 0.0f),        \
                                           fmaxf(acc[mt][nt][3], 0.0f));       \
            acc[mt][nt][0] = 0.0f; acc[mt][nt][1] = 0.0f;                      \
            acc[mt][nt][2] = 0.0f; acc[mt][nt][3] = 0.0f;                      \
        }                                                                      \
} while (0)

    // Layer 0: E @ W0 -> B1 (ReLU)
    RUN_LAYER(0, 4, sb + E_OFF, EPITCH);
    EPILOGUE_RELU(B1w);
    __syncthreads();                      // (2) B1 ready

    // Layer 1: B1 @ W1 -> B2 (ping-pong: no WAR barrier)
    RUN_LAYER(4, 16, sb + B1_OFF, BPITCH);
    EPILOGUE_RELU(B2w);
    __syncthreads();                      // (3) B2 ready

    // Layer 2 + fused final dot from fp32 accumulators.
    RUN_LAYER(20, 16, sb + B2_OFF, BPITCH);
    #pragma unroll
    for (int mt = 0; mt < 2; ++mt) {
        float s0 = 0.0f, s1 = 0.0f;
        #pragma unroll
        for (int nt = 0; nt < 8; ++nt) {
            const int c = nb + nt * 8 + 2 * tig;
            const float wA = W3s[c], wB = W3s[c + 1];
            s0 = fmaf(fmaxf(acc[mt][nt][0], 0.0f), wA, s0);
            s0 = fmaf(fmaxf(acc[mt][nt][1], 0.0f), wB, s0);
            s1 = fmaf(fmaxf(acc[mt][nt][2], 0.0f), wA, s1);
            s1 = fmaf(fmaxf(acc[mt][nt][3], 0.0f), wB, s1);
        }
        s0 += __shfl_xor_sync(0xffffffffu, s0, 1);
        s0 += __shfl_xor_sync(0xffffffffu, s0, 2);
        s1 += __shfl_xor_sync(0xffffffffu, s1, 1);
        s1 += __shfl_xor_sync(0xffffffffu, s1, 2);
        if (tig == 0) {
            const int r0 = mb + mt * 16 + grp;
            part[r0 * 4 + nq]       = s0;
            part[(r0 + 8) * 4 + nq] = s1;
        }
    }
    __syncthreads();                      // (4) partials ready

    if (tid < 64) {
        const float* p4 = part + tid * 4;
        out[blockIdx.x * 64 + tid] = (p4[0] + p4[1]) + (p4[2] + p4[3]);
    }
}

// --------------------------------- launcher ---------------------------------
extern "C" void kernel_launch(void* const* d_in, const int* in_sizes, int n_in,
                              void* d_out, int out_size)
{
    const float* x     = (const float*)d_in[0];
    const float* table = (const float*)d_in[1];
    const float* W0    = (const float*)d_in[2];
    const float* W1    = (const float*)d_in[3];
    const float* W2    = (const float*)d_in[4];
    const float* W3    = (const float*)d_in[5];
    float*       out   = (float*)d_out;

    LevelParams lp;
    for (int l = 0; l < NLEV; ++l) {
        double sc = 16.0 * pow(1.2599210739135742, (double)l) - 1.0;
        int res = (int)ceil(sc) + 1;
        long long sz = (long long)res * (long long)res;
        sz = ((sz + 7) / 8) * 8;
        if (sz > (1LL << 19)) sz = 1LL << 19;
        lp.scale[l] = (float)sc;
        lp.res[l]   = res;
        lp.size[l]  = (int)sz;
    }

    wt_prep<<<288, 256>>>(W0, W1, W2);
    tb_prep<<<256, 256>>>(table);

    cudaFuncSetAttribute(nf_main, cudaFuncAttributeMaxDynamicSharedMemorySize,
                         SMEM_BYTES);
    nf_main<<<NPTS / 64, THREADS, SMEM_BYTES>>>(x, W3, out, lp);
}

// round 17
// speedup vs baseline: 1.6771x; 1.0217x over previous
#include <cuda_runtime.h>
#include <cuda_fp16.h>
#include <cstdint>
#include <math.h>

// NeuralField fused: hashgrid encode + 3-layer MLP on mma.sync FP16 (fp32 acc)
// + fused final dot. CTA = 64 points, 256 threads (8 warps).
// THIS ROUND: warp tile 64x32 — each warp owns a DISTINCT N-octant, so B
// fragment LDGs are duplicate-free (halves weight traffic). A via 4x
// ldmatrix.x4 over XOR-swizzled activations. 2 CTAs/SM. Prep fused into one
// kernel.

#define NLEV    8
#define NPTS    262144
#define THREADS 256

#define BPITCH 128     // B1/B2 words per row (256 halves)
#define EPITCH 32      // E words per row (64 halves)

#define B1_OFF   0
#define B2_OFF   32768
#define E_OFF    65536
#define W3_OFF   73728
#define PART_OFF 74752
#define SMEM_BYTES 76800     // 2 CTAs/SM

struct LevelParams { float scale[NLEV]; int res[NLEV]; int size[NLEV]; };

// fragment-major weights (half2): [g(36)][nq8(8)][j(2)][lane(32)][e(4)]
__device__ uint32_t g_Wf[36 * 2048];
// fp16 table: one uint4 (8 halves) per (level, row)
__device__ uint4 g_Th[NLEV * 8192];

// ------------------------------- helpers -----------------------------------
__device__ __forceinline__ uint32_t smem_u32(const void* p) {
    uint32_t a;
    asm("{ .reg .u64 t; cvta.to.shared.u64 t, %1; cvt.u32.u64 %0, t; }"
        : "=r"(a) : "l"(p));
    return a;
}
__device__ __forceinline__ void mma_f16(float* d, uint32_t a0, uint32_t a1,
                                        uint32_t a2, uint32_t a3,
                                        uint32_t b0, uint32_t b1) {
    asm volatile(
        "mma.sync.aligned.m16n8k16.row.col.f32.f16.f16.f32 "
        "{%0,%1,%2,%3}, {%4,%5,%6,%7}, {%8,%9}, {%0,%1,%2,%3};"
        : "+f"(d[0]), "+f"(d[1]), "+f"(d[2]), "+f"(d[3])
        : "r"(a0), "r"(a1), "r"(a2), "r"(a3), "r"(b0), "r"(b1));
}
__device__ __forceinline__ void ldsm4(uint32_t* r, uint32_t addr) {
    asm volatile("ldmatrix.sync.aligned.m8n8.x4.shared.b16 {%0,%1,%2,%3}, [%4];"
                 : "=r"(r[0]), "=r"(r[1]), "=r"(r[2]), "=r"(r[3]) : "r"(addr));
}
__device__ __forceinline__ uint32_t packh2(float lo, float hi) {
    __half2 h = __halves2half2(__float2half_rn(lo), __float2half_rn(hi));
    return *(uint32_t*)&h;
}

// ---------------- prep (single kernel): weights + table ---------------------
__global__ void prep_all(const float* __restrict__ W0,
                         const float* __restrict__ W1,
                         const float* __restrict__ W2,
                         const float* __restrict__ table)
{
    const int idx = blockIdx.x * 256 + threadIdx.x;    // 0 .. 139263
    if (idx < 36 * 2048) {
        // weights: [g][nq8(8)][j(2)][lane(32)][e(4)]
        const int g    = idx >> 11;
        const int r    = idx & 2047;
        const int nq8  = r >> 8;
        const int j    = (r >> 7) & 1;
        const int lane = (r >> 2) & 31;
        const int e    = r & 3;
        const int grp  = lane >> 2, tig = lane & 3;
        const int i8   = j * 4 + e;
        const int nt   = i8 >> 1;
        const int b    = i8 & 1;

        const float* W; int kc;
        if (g < 4)       { W = W0; kc = g * 16; }
        else if (g < 20) { W = W1; kc = (g - 4) * 16; }
        else             { W = W2; kc = (g - 20) * 16; }

        const int k = kc + b * 8 + 2 * tig;            // halves (k, k+1)
        const int n = nq8 * 32 + nt * 8 + grp;
        g_Wf[idx] = packh2(W[k * 256 + n], W[(k + 1) * 256 + n]);
    } else {
        const int r = idx - 36 * 2048;                 // 0 .. 65535 table rows
        const float4 t0 = ((const float4*)table)[r * 2];
        const float4 t1 = ((const float4*)table)[r * 2 + 1];
        uint4 v;
        v.x = packh2(t0.x, t0.y);
        v.y = packh2(t0.z, t0.w);
        v.z = packh2(t1.x, t1.y);
        v.w = packh2(t1.z, t1.w);
        g_Th[r] = v;
    }
}

// --------------------------------- main kernel ------------------------------
__global__ __launch_bounds__(THREADS, 2)
void nf_main(const float* __restrict__ x,
             const float* __restrict__ W3, float* __restrict__ out, LevelParams lp)
{
    extern __shared__ char smem[];
    uint32_t* B1w  = (uint32_t*)(smem + B1_OFF);
    uint32_t* B2w  = (uint32_t*)(smem + B2_OFF);
    uint32_t* Ew   = (uint32_t*)(smem + E_OFF);
    float*    W3s  = (float*)(smem + W3_OFF);
    float*    part = (float*)(smem + PART_OFF);
    const uint32_t sb = smem_u32(smem);

    const int tid  = threadIdx.x;
    const int wid  = tid >> 5;           // = nq8, N-octant 0..7
    const int lane = tid & 31;
    const int grp  = lane >> 2;
    const int tig  = lane & 3;
    const int nq8  = wid;
    const int nb   = nq8 * 32;

    // ldmatrix per-lane constants
    const int lrow = lane & 15;
    const int l4   = (lane >> 4) << 2;
    const int swz  = (lane & 7) << 2;

    W3s[tid] = W3[tid];

    // ---------------- Encode: 4 threads/point, 2 levels/thread --------------
    {
        const int p    = tid & 63;
        const int quad = tid >> 6;
        const int gp   = blockIdx.x * 64 + p;
        const float xx = x[2 * gp];
        const float yy = x[2 * gp + 1];
        const int psw  = (p & 7) << 2;

        #pragma unroll
        for (int li = 0; li < 2; ++li) {
            const int l     = quad * 2 + li;
            const float s   = lp.scale[l];
            const int res   = lp.res[l];
            const int size  = lp.size[l];

            const float posx = xx * s + 0.5f;
            const float posy = yy * s + 0.5f;
            const float gx = floorf(posx), gy = floorf(posy);
            const float fx = posx - gx,    fy = posy - gy;
            const int   ix = (int)gx,      iy = (int)gy;
            const float wx = fx * fx * (3.0f - 2.0f * fx);
            const float wy = fy * fy * (3.0f - 2.0f * fy);

            float wc[4];
            uint4 v[4];
            #pragma unroll
            for (int c = 0; c < 4; ++c) {
                const int dx = c >> 1, dy = c & 1;
                wc[c] = (dx ? wx : 1.0f - wx) * (dy ? wy : 1.0f - wy);
                int idx = (ix + dx) + (iy + dy) * res;   // < 2*size (dense)
                if (idx >= size) idx -= size;
                v[c] = __ldg(&g_Th[l * 8192 + idx]);
            }

            float f[8];
            #pragma unroll
            for (int j = 0; j < 8; ++j) f[j] = 0.0f;
            #pragma unroll
            for (int c = 0; c < 4; ++c) {
                const float w = wc[c];
                const __half2* h = (const __half2*)&v[c];
                const float2 p0 = __half22float2(h[0]);
                const float2 p1 = __half22float2(h[1]);
                const float2 p2 = __half22float2(h[2]);
                const float2 p3 = __half22float2(h[3]);
                f[0] += w * p0.x; f[1] += w * p0.y;
                f[2] += w * p1.x; f[3] += w * p1.y;
                f[4] += w * p2.x; f[5] += w * p2.y;
                f[6] += w * p3.x; f[7] += w * p3.y;
            }
            uint4 uv;
            uv.x = packh2(f[0], f[1]);
            uv.y = packh2(f[2], f[3]);
            uv.z = packh2(f[4], f[5]);
            uv.w = packh2(f[6], f[7]);
            const int physw = p * EPITCH + ((l * 4) ^ psw);
            *(uint4*)&Ew[physw] = uv;                    // STS.128, conflict-free
        }
    }

    float acc[4][4][4];
    #pragma unroll
    for (int mt = 0; mt < 4; ++mt)
        #pragma unroll
        for (int nt = 0; nt < 4; ++nt)
            #pragma unroll
            for (int q = 0; q < 4; ++q) acc[mt][nt][q] = 0.0f;

    // B fragments: duplicate-free per-warp LDG, register double-buffer.
    float bf[2][8];

#define LOADB(G, SLOT) do {                                                    \
    const float4* _s = ((const float4*)g_Wf) + (G) * 512 + nq8 * 64 + lane;    \
    *(float4*)&bf[SLOT][0] = __ldg(_s);                                        \
    *(float4*)&bf[SLOT][4] = __ldg(_s + 32);                                   \
} while (0)

    LOADB(0, 0);
    __syncthreads();                      // (1) E visible to all warps

#define RUN_LAYER(GBASE, NG, ABYTE, APITCH) do {                               \
    const uint32_t rbase = (ABYTE) + (uint32_t)lrow * ((APITCH) * 4);          \
    _Pragma("unroll 2")                                                        \
    for (int lg = 0; lg < (NG); ++lg) {                                        \
        const int cur = ((GBASE) + lg) & 1;                                    \
        if ((GBASE) + lg + 1 < 36) LOADB((GBASE) + lg + 1, cur ^ 1);           \
        const uint32_t wsw = (uint32_t)((lg * 8 + l4) ^ swz) << 2;             \
        uint32_t a[4][4];                                                      \
        _Pragma("unroll")                                                      \
        for (int mt = 0; mt < 4; ++mt)                                         \
            ldsm4(a[mt], rbase + (uint32_t)(mt * 16) * ((APITCH) * 4) + wsw);  \
        _Pragma("unroll")                                                      \
        for (int nt = 0; nt < 4; ++nt) {                                       \
            const uint32_t b0 = __float_as_uint(bf[cur][nt * 2]);              \
            const uint32_t b1 = __float_as_uint(bf[cur][nt * 2 + 1]);          \
            _Pragma("unroll")                                                  \
            for (int mt = 0; mt < 4; ++mt)                                     \
                mma_f16(acc[mt][nt], a[mt][0], a[mt][1], a[mt][2], a[mt][3],   \
                        b0, b1);                                               \
        }                                                                      \
    }                                                                          \
} while (0)

#define EPILOGUE_RELU(DW) do {                                                 \
    _Pragma("unroll")                                                          \
    for (int mt = 0; mt < 4; ++mt)                                             \
        _Pragma("unroll")                                                      \
        for (int nt = 0; nt < 4; ++nt) {                                       \
            const int r0 = mt * 16 + grp;                                      \
            const int w  = nq8 * 16 + nt * 4 + tig;                            \
            const int ph = r0 * BPITCH + (w ^ (grp << 2));                     \
            (DW)[ph]              = packh2(fmaxf(acc[mt][nt][0], 0.0f),        \
                                           fmaxf(acc[mt][nt][1], 0.0f));       \
            (DW)[ph + 8 * BPITCH] = packh2(fmaxf(acc[mt][nt][2], 0.0f),        \
                                           fmaxf(acc[mt][nt][3], 0.0f));       \
            acc[mt][nt][0] = 0.0f; acc[mt][nt][1] = 0.0f;                      \
            acc[mt][nt][2] = 0.0f; acc[mt][nt][3] = 0.0f;                      \
        }                                                                      \
} while (0)

    // Layer 0: E @ W0 -> B1 (ReLU)
    RUN_LAYER(0, 4, sb + E_OFF, EPITCH);
    EPILOGUE_RELU(B1w);
    __syncthreads();                      // (2) B1 ready

    // Layer 1: B1 @ W1 -> B2 (ping-pong)
    RUN_LAYER(4, 16, sb + B1_OFF, BPITCH);
    EPILOGUE_RELU(B2w);
    __syncthreads();                      // (3) B2 ready

    // Layer 2 + fused final dot from fp32 accumulators.
    RUN_LAYER(20, 16, sb + B2_OFF, BPITCH);
    #pragma unroll
    for (int mt = 0; mt < 4; ++mt) {
        float s0 = 0.0f, s1 = 0.0f;
        #pragma unroll
        for (int nt = 0; nt < 4; ++nt) {
            const int c = nb + nt * 8 + 2 * tig;
            const float wA = W3s[c], wB = W3s[c + 1];
            s0 = fmaf(fmaxf(acc[mt][nt][0], 0.0f), wA, s0);
            s0 = fmaf(fmaxf(acc[mt][nt][1], 0.0f), wB, s0);
            s1 = fmaf(fmaxf(acc[mt][nt][2], 0.0f), wA, s1);
            s1 = fmaf(fmaxf(acc[mt][nt][3], 0.0f), wB, s1);
        }
        s0 += __shfl_xor_sync(0xffffffffu, s0, 1);
        s0 += __shfl_xor_sync(0xffffffffu, s0, 2);
        s1 += __shfl_xor_sync(0xffffffffu, s1, 1);
        s1 += __shfl_xor_sync(0xffffffffu, s1, 2);
        if (tig == 0) {
            const int r0 = mt * 16 + grp;
            part[r0 * 8 + nq8]       = s0;
            part[(r0 + 8) * 8 + nq8] = s1;
        }
    }
    __syncthreads();                      // (4) partials ready

    if (tid < 64) {
        const float4* p8 = (const float4*)(part + tid * 8);
        const float4 a4 = p8[0], b4 = p8[1];
        out[blockIdx.x * 64 + tid] =
            ((a4.x + a4.y) + (a4.z + a4.w)) + ((b4.x + b4.y) + (b4.z + b4.w));
    }
}

// --------------------------------- launcher ---------------------------------
extern "C" void kernel_launch(void* const* d_in, const int* in_sizes, int n_in,
                              void* d_out, int out_size)
{
    const float* x     = (const float*)d_in[0];
    const float* table = (const float*)d_in[1];
    const float* W0    = (const float*)d_in[2];
    const float* W1    = (const float*)d_in[3];
    const float* W2    = (const float*)d_in[4];
    const float* W3    = (const float*)d_in[5];
    float*       out   = (float*)d_out;

    LevelParams lp;
    for (int l = 0; l < NLEV; ++l) {
        double sc = 16.0 * pow(1.2599210739135742, (double)l) - 1.0;
        int res = (int)ceil(sc) + 1;
        long long sz = (long long)res * (long long)res;
        sz = ((sz + 7) / 8) * 8;
        if (sz > (1LL << 19)) sz = 1LL << 19;
        lp.scale[l] = (float)sc;
        lp.res[l]   = res;
        lp.size[l]  = (int)sz;
    }

    prep_all<<<544, 256>>>(W0, W1, W2, table);   // 544*256 = 139264 items

    cudaFuncSetAttribute(nf_main, cudaFuncAttributeMaxDynamicSharedMemorySize,
                         SMEM_BYTES);
    nf_main<<<NPTS / 64, THREADS, SMEM_BYTES>>>(x, W3, out, lp);
}